// round 8
// baseline (speedup 1.0000x reference)
#include <cuda_runtime.h>
#include <cstdint>

#define N_NODES 2048
#define HID 1024
#define LDQ 1026          // Wq row stride (HID + 2)
#define T_STEPS 2304      // N + N/8
#define TOUR_LEN 2305
#define COEF 0.015625f    // ALPHA / sqrt(HID) = 0.5/32, exact power of two
#define KEY_SENTINEL (-2147483647 - 1)   // INT_MIN < ordkey(-inf)

// Scratch (allocation-free rule: __device__ globals)
static __device__ float g_K[N_NODES * HID];      // 8 MB  K = E Wk^T + bk
static __device__ float g_A[N_NODES * HID];      // 8 MB  A = K Wq1
static __device__ float g_P[N_NODES * N_NODES];  // 16 MB P[last][cand] = c*E A^T
static __device__ float g_v[N_NODES];
static __device__ float g_w[N_NODES];

// ---------------------------------------------------------------------------
// f32x2 packed helpers (FFMA2 — ptxas only emits via PTX fma.rn.f32x2).
// Per-lane IEEE fma.rn => bitwise identical to scalar fmaf chains.
// ---------------------------------------------------------------------------
__device__ __forceinline__ unsigned long long f2dup(float x) {
    unsigned long long r;
    asm("mov.b64 %0, {%1, %1};" : "=l"(r) : "f"(x));
    return r;
}
__device__ __forceinline__ void fma2(unsigned long long& d,
                                     unsigned long long a,
                                     unsigned long long b) {
    asm("fma.rn.f32x2 %0, %1, %2, %0;" : "+l"(d) : "l"(a), "l"(b));
}
__device__ __forceinline__ void f2unpack(unsigned long long v, float& lo, float& hi) {
    asm("mov.b64 {%0, %1}, %2;" : "=f"(lo), "=f"(hi) : "l"(v));
}

// Shared compute micro-kernel: 16 k-steps on buffer s, 8x8 microtile.
#define MICRO_COMPUTE(S)                                                      \
    do {                                                                      \
        _Pragma("unroll")                                                     \
        for (int kk = 0; kk < 16; kk++) {                                     \
            float4 a0 = *(const float4*)&As[S][kk][ty * 8];                   \
            float4 a1 = *(const float4*)&As[S][kk][ty * 8 + 4];               \
            ulonglong2 q0 = *(const ulonglong2*)&Bs[S][kk][tx * 8];           \
            ulonglong2 q1 = *(const ulonglong2*)&Bs[S][kk][tx * 8 + 4];       \
            float av[8] = {a0.x, a0.y, a0.z, a0.w, a1.x, a1.y, a1.z, a1.w};   \
            _Pragma("unroll")                                                 \
            for (int i = 0; i < 8; i++) {                                     \
                unsigned long long ad = f2dup(av[i]);                         \
                fma2(acc[i][0], ad, q0.x);                                    \
                fma2(acc[i][1], ad, q0.y);                                    \
                fma2(acc[i][2], ad, q1.x);                                    \
                fma2(acc[i][3], ad, q1.y);                                    \
            }                                                                 \
        }                                                                     \
    } while (0)

#define EPILOGUE()                                                            \
    do {                                                                      \
        _Pragma("unroll")                                                     \
        for (int i = 0; i < 8; i++) {                                         \
            int row = bm + ty * 8 + i;                                        \
            float o[8];                                                       \
            _Pragma("unroll")                                                 \
            for (int j = 0; j < 4; j++) f2unpack(acc[i][j], o[2*j], o[2*j+1]);\
            int col = bn + tx * 8;                                            \
            float4 o0, o1;                                                    \
            o0.x = o[0]*scale; o0.y = o[1]*scale; o0.z = o[2]*scale; o0.w = o[3]*scale; \
            o1.x = o[4]*scale; o1.y = o[5]*scale; o1.z = o[6]*scale; o1.w = o[7]*scale; \
            if (HAS_BIAS) {                                                   \
                o0.x += bias[col+0]; o0.y += bias[col+1];                     \
                o0.z += bias[col+2]; o0.w += bias[col+3];                     \
                o1.x += bias[col+4]; o1.y += bias[col+5];                     \
                o1.z += bias[col+6]; o1.w += bias[col+7];                     \
            }                                                                 \
            *(float4*)(C + (size_t)row * ldc + col)     = o0;                 \
            *(float4*)(C + (size_t)row * ldc + col + 4) = o1;                 \
        }                                                                     \
    } while (0)

// ---------------------------------------------------------------------------
// TN GEMM: C[m,n] = scale * sum_k A[m,k]*B[n,k] (+ bias[n]).
// ---------------------------------------------------------------------------
template <bool HAS_BIAS>
__global__ __launch_bounds__(256)
void gemm_tn(const float* __restrict__ A, const float* __restrict__ B,
             const float* __restrict__ bias, float* __restrict__ C,
             int Kd, int lda, int ldb, int ldc, float scale)
{
    __shared__ __align__(16) float As[2][16][128];
    __shared__ __align__(16) float Bs[2][16][128];
    const int tid = threadIdx.x;
    const int bm = blockIdx.y * 128, bn = blockIdx.x * 128;
    const int tx = tid & 15, ty = tid >> 4;
    const int ar = tid >> 2, ac4 = tid & 3;

    unsigned long long acc[8][4];
#pragma unroll
    for (int i = 0; i < 8; i++)
#pragma unroll
        for (int j = 0; j < 4; j++) acc[i][j] = 0ull;

    const float* Ap = A + (size_t)(bm + ar) * lda + ac4 * 4;
    const float* Bp = B + (size_t)(bn + ar) * ldb + ac4 * 4;
    float4 ra0, ra1, rb0, rb1;

#define LOADT(K0)                                                             \
    do {                                                                      \
        ra0 = __ldg((const float4*)(Ap + (K0)));                              \
        ra1 = __ldg((const float4*)(Ap + (size_t)64 * lda + (K0)));           \
        rb0 = __ldg((const float4*)(Bp + (K0)));                              \
        rb1 = __ldg((const float4*)(Bp + (size_t)64 * ldb + (K0)));           \
    } while (0)
#define STORET(S)                                                             \
    do {                                                                      \
        As[S][ac4*4+0][ar] = ra0.x; As[S][ac4*4+1][ar] = ra0.y;               \
        As[S][ac4*4+2][ar] = ra0.z; As[S][ac4*4+3][ar] = ra0.w;               \
        As[S][ac4*4+0][ar+64] = ra1.x; As[S][ac4*4+1][ar+64] = ra1.y;         \
        As[S][ac4*4+2][ar+64] = ra1.z; As[S][ac4*4+3][ar+64] = ra1.w;         \
        Bs[S][ac4*4+0][ar] = rb0.x; Bs[S][ac4*4+1][ar] = rb0.y;               \
        Bs[S][ac4*4+2][ar] = rb0.z; Bs[S][ac4*4+3][ar] = rb0.w;               \
        Bs[S][ac4*4+0][ar+64] = rb1.x; Bs[S][ac4*4+1][ar+64] = rb1.y;         \
        Bs[S][ac4*4+2][ar+64] = rb1.z; Bs[S][ac4*4+3][ar+64] = rb1.w;         \
    } while (0)

    LOADT(0);
    STORET(0);
    __syncthreads();
    const int KT = Kd / 16;
#pragma unroll 1
    for (int kt = 0; kt < KT; kt++) {
        const int s = kt & 1;
        const bool more = (kt + 1) < KT;
        if (more) LOADT((kt + 1) * 16);
        MICRO_COMPUTE(s);
        if (more) { STORET(s ^ 1); __syncthreads(); }
    }
    EPILOGUE();
#undef LOADT
#undef STORET
}

// ---------------------------------------------------------------------------
// NN GEMM: C[m,n] = sum_k A[m,k]*B[k,n], B row stride ldb (=LDQ).
// ---------------------------------------------------------------------------
__global__ __launch_bounds__(256)
void gemm_nn(const float* __restrict__ A, const float* __restrict__ B,
             float* __restrict__ C, int Kd, int lda, int ldb, int ldc)
{
    __shared__ __align__(16) float As[2][16][128];
    __shared__ __align__(16) float Bs[2][16][128];
    const int tid = threadIdx.x;
    const int bm = blockIdx.y * 128, bn = blockIdx.x * 128;
    const int tx = tid & 15, ty = tid >> 4;
    const int ar = tid >> 2, ac4 = tid & 3;
    const int br = tid >> 6, bc2 = tid & 63;
    const float scale = 1.0f;
    const bool HAS_BIAS = false;
    const float* bias = nullptr;

    unsigned long long acc[8][4];
#pragma unroll
    for (int i = 0; i < 8; i++)
#pragma unroll
        for (int j = 0; j < 4; j++) acc[i][j] = 0ull;

    const float* Ap  = A + (size_t)(bm + ar) * lda + ac4 * 4;
    const float* Bpn = B + (size_t)br * ldb + bn + bc2 * 2;
    float4 ra0, ra1;
    float2 rbn[4];

#define LOADN(K0)                                                             \
    do {                                                                      \
        ra0 = __ldg((const float4*)(Ap + (K0)));                              \
        ra1 = __ldg((const float4*)(Ap + (size_t)64 * lda + (K0)));           \
        _Pragma("unroll")                                                     \
        for (int p = 0; p < 4; p++)                                           \
            rbn[p] = *(const float2*)(Bpn + (size_t)((K0) + p * 4) * ldb);    \
    } while (0)
#define STOREN(S)                                                             \
    do {                                                                      \
        As[S][ac4*4+0][ar] = ra0.x; As[S][ac4*4+1][ar] = ra0.y;               \
        As[S][ac4*4+2][ar] = ra0.z; As[S][ac4*4+3][ar] = ra0.w;               \
        As[S][ac4*4+0][ar+64] = ra1.x; As[S][ac4*4+1][ar+64] = ra1.y;         \
        As[S][ac4*4+2][ar+64] = ra1.z; As[S][ac4*4+3][ar+64] = ra1.w;         \
        _Pragma("unroll")                                                     \
        for (int p = 0; p < 4; p++) {                                         \
            Bs[S][br + p*4][bc2*2 + 0] = rbn[p].x;                            \
            Bs[S][br + p*4][bc2*2 + 1] = rbn[p].y;                            \
        }                                                                     \
    } while (0)

    LOADN(0);
    STOREN(0);
    __syncthreads();
    const int KT = Kd / 16;
#pragma unroll 1
    for (int kt = 0; kt < KT; kt++) {
        const int s = kt & 1;
        const bool more = (kt + 1) < KT;
        if (more) LOADN((kt + 1) * 16);
        MICRO_COMPUTE(s);
        if (more) { STOREN(s ^ 1); __syncthreads(); }
    }
    EPILOGUE();
#undef LOADN
#undef STOREN
}

// ---------------------------------------------------------------------------
// v[i] = c * sum_h K[i,h]*Wq[h,1024];  w[i] = c * sum_h K[i,h]*bq[h]
// ---------------------------------------------------------------------------
__global__ __launch_bounds__(256)
void vw_kernel(const float* __restrict__ Wq, const float* __restrict__ bq)
{
    __shared__ float scol[HID];
    __shared__ float sbq[HID];
    const int tid = threadIdx.x;
    for (int h = tid; h < HID; h += 256) {
        scol[h] = Wq[(size_t)h * LDQ + HID];
        sbq[h]  = bq[h];
    }
    __syncthreads();
    const int warp = tid >> 5, lane = tid & 31;
    const int row = blockIdx.x * 8 + warp;
    const float* Kr = g_K + (size_t)row * HID;
    float vv = 0.f, ww = 0.f;
#pragma unroll 4
    for (int m = 0; m < HID / 32; m++) {
        int h = lane + m * 32;
        float k = Kr[h];
        vv = fmaf(k, scol[h], vv);
        ww = fmaf(k, sbq[h], ww);
    }
#pragma unroll
    for (int off = 16; off; off >>= 1) {
        vv += __shfl_xor_sync(0xffffffffu, vv, off);
        ww += __shfl_xor_sync(0xffffffffu, ww, off);
    }
    if (lane == 0) { g_v[row] = COEF * vv; g_w[row] = COEF * ww; }
}

// ---------------------------------------------------------------------------
// Decoder helpers: SIGNED-order-preserving float<->int key.
// ---------------------------------------------------------------------------
__device__ __forceinline__ int ordkey(float f) {
    int b = __float_as_int(f);
    return b ^ ((b >> 31) & 0x7FFFFFFF);
}
__device__ __forceinline__ float unord(int k) {
    int b = k ^ ((k >> 31) & 0x7FFFFFFF);
    return __int_as_float(b);
}
__device__ __forceinline__ int redux_max_i32(int v) {
    int r;
    asm("redux.sync.max.s32 %0, %1, 0xffffffff;" : "=r"(r) : "r"(v));
    return r;
}

// ---------------------------------------------------------------------------
// Sequential decoder v3: 1 block x 128 threads, 16 candidates/thread.
// s = fmaf(u, v[i], P[last,i] + w[i])  -- EXACT R1 arithmetic.
// Tree argmax (leftmost-max), demand piggybacked, one barrier per step.
// ---------------------------------------------------------------------------
__global__ __launch_bounds__(128)
void decode_kernel(const float* __restrict__ demands,
                   const int* __restrict__ cap_ptr,
                   const int* __restrict__ depot_ptr,
                   float* __restrict__ out)
{
    __shared__ __align__(16) float sdepot[N_NODES];   // P[depot,:] pinned
    __shared__ __align__(16) int4 red[2][4];          // per-warp (key, idx, demand, pad)

    const int tid = threadIdx.x;

    int ci = cap_ptr ? __ldg(cap_ptr) : 40;
    float cap = (ci >= 0 && ci < (1 << 23)) ? (float)ci : __int_as_float(ci);
    int depot = depot_ptr ? __ldg(depot_ptr) : 0;
    if ((unsigned)depot >= N_NODES) depot = 0;

    for (int i = tid; i < N_NODES; i += 128)
        sdepot[i] = g_P[(size_t)depot * N_NODES + i];

    // per-thread candidate block [tid*16, tid*16+16): invariants in registers
    float rv[16], rw[16], rd[16];
#pragma unroll
    for (int q = 0; q < 4; q++) {
        float4 a = ((const float4*)(g_v + tid * 16))[q];
        rv[4*q+0]=a.x; rv[4*q+1]=a.y; rv[4*q+2]=a.z; rv[4*q+3]=a.w;
        float4 b = ((const float4*)(g_w + tid * 16))[q];
        rw[4*q+0]=b.x; rw[4*q+1]=b.y; rw[4*q+2]=b.z; rw[4*q+3]=b.w;
        float4 c = ((const float4*)(demands + tid * 16))[q];
        rd[4*q+0]=c.x; rd[4*q+1]=c.y; rd[4*q+2]=c.z; rd[4*q+3]=c.w;
    }

    unsigned vis = 0;                     // 16 visited bits for [tid*16, tid*16+16)
    if ((depot >> 4) == tid) vis = 1u << (depot & 15);
    int last = depot;
    bool last_is_depot = true;
    float load = cap;
    int count = 1;
    if (tid == 0) out[0] = (float)depot;
    __syncthreads();

    const int lane = tid & 31, warp = tid >> 5;
    int tstop = T_STEPS;

    for (int t = 0; t < T_STEPS; t++) {
        // ---- fetch P row slice (16 floats = 4x LDG.128, MLP=4) ----
        float pv[16];
        if (last_is_depot) {
#pragma unroll
            for (int q = 0; q < 4; q++) {
                float4 p = *(const float4*)&sdepot[tid * 16 + 4 * q];
                pv[4*q+0]=p.x; pv[4*q+1]=p.y; pv[4*q+2]=p.z; pv[4*q+3]=p.w;
            }
        } else {
            const float4* Pr = (const float4*)(g_P + (size_t)last * N_NODES + tid * 16);
#pragma unroll
            for (int q = 0; q < 4; q++) {
                float4 p = __ldg(Pr + q);
                pv[4*q+0]=p.x; pv[4*q+1]=p.y; pv[4*q+2]=p.z; pv[4*q+3]=p.w;
            }
        }

        const float u = load / cap;    // overlaps LDG latency (independent)

        // keys with feasibility folded in
        int key[16];
#pragma unroll
        for (int j = 0; j < 16; j++) {
            float s = fmaf(u, rv[j], pv[j] + rw[j]);   // exact R1 expression
            bool feas = !((vis >> j) & 1u) && (rd[j] <= load);
            key[j] = feas ? ordkey(s) : KEY_SENTINEL;
        }
        // 4-level leftmost-max tree carrying (key, idx, demand)
        int k8[8], i8[8]; float d8[8];
#pragma unroll
        for (int j = 0; j < 8; j++) {
            bool l = key[2*j] >= key[2*j+1];
            k8[j] = l ? key[2*j] : key[2*j+1];
            i8[j] = l ? 2*j : 2*j+1;
            d8[j] = l ? rd[2*j] : rd[2*j+1];
        }
        int k4[4], i4[4]; float d4[4];
#pragma unroll
        for (int j = 0; j < 4; j++) {
            bool l = k8[2*j] >= k8[2*j+1];
            k4[j] = l ? k8[2*j] : k8[2*j+1];
            i4[j] = l ? i8[2*j] : i8[2*j+1];
            d4[j] = l ? d8[2*j] : d8[2*j+1];
        }
        int k2[2], i2[2]; float d2[2];
#pragma unroll
        for (int j = 0; j < 2; j++) {
            bool l = k4[2*j] >= k4[2*j+1];
            k2[j] = l ? k4[2*j] : k4[2*j+1];
            i2[j] = l ? i4[2*j] : i4[2*j+1];
            d2[j] = l ? d4[2*j] : d4[2*j+1];
        }
        bool l0 = k2[0] >= k2[1];
        int bestk = l0 ? k2[0] : k2[1];
        int bestj = l0 ? i2[0] : i2[1];
        float bestd = l0 ? d2[0] : d2[1];
        int besti = tid * 16 + bestj;

        // warp argmax: redux + ballot (lowest lane = lowest candidate index)
        int m = redux_max_i32(bestk);
        unsigned bal = __ballot_sync(0xffffffffu, bestk == m);
        int src = __ffs(bal) - 1;
        int wi = __shfl_sync(0xffffffffu, besti, src);
        float wd = __shfl_sync(0xffffffffu, bestd, src);
        if (lane == 0) red[t & 1][warp] = make_int4(m, wi, __float_as_int(wd), 0);
        __syncthreads();

        // cross-warp scan (4 entries, strict > keeps earlier warp on ties)
        int4 a = red[t & 1][0];
        int4 b = red[t & 1][1];
        int4 c = red[t & 1][2];
        int4 d = red[t & 1][3];
        if (b.x > a.x) a = b;
        if (c.x > a.x) a = c;
        if (d.x > a.x) a = d;
        int gk = a.x, gi = a.y;

        if (gk > KEY_SENTINEL) {
            last = gi;
            last_is_depot = false;
            load -= __int_as_float(a.z);
            count++;
            if ((gi >> 4) == tid) vis |= 1u << (gi & 15);
            if (tid == 0) { out[1 + t] = (float)gi; out[TOUR_LEN + t] = unord(gk); }
        } else {
            last = depot;
            last_is_depot = true;
            load = cap;
            if (tid == 0) { out[1 + t] = (float)depot; out[TOUR_LEN + t] = 0.0f; }
            if (count == N_NODES) { tstop = t + 1; break; }
        }
    }
    for (int t2 = tstop + tid; t2 < T_STEPS; t2 += 128) {
        out[1 + t2] = (float)depot;
        out[TOUR_LEN + t2] = 0.0f;
    }
}

// ---------------------------------------------------------------------------
extern "C" void kernel_launch(void* const* d_in, const int* in_sizes, int n_in,
                              void* d_out, int out_size)
{
    const float* node_emb = (const float*)d_in[0];
    const float* demands  = (const float*)d_in[1];
    const float* Wq       = (const float*)d_in[2];
    const float* bq       = (const float*)d_in[3];
    const float* Wk       = (const float*)d_in[4];
    const float* bk       = (const float*)d_in[5];
    const int* capi = (n_in > 6) ? (const int*)d_in[6] : nullptr;
    const int* depi = (n_in > 7) ? (const int*)d_in[7] : nullptr;
    float* out = (float*)d_out;

    float *pK = nullptr, *pA = nullptr, *pP = nullptr;
    cudaGetSymbolAddress((void**)&pK, g_K);
    cudaGetSymbolAddress((void**)&pA, g_A);
    cudaGetSymbolAddress((void**)&pP, g_P);

    // K = E Wk^T + bk           [2048,1024]
    gemm_tn<true><<<dim3(HID / 128, N_NODES / 128), 256>>>(
        node_emb, Wk, bk, pK, HID, HID, HID, HID, 1.0f);
    // A = K @ Wq[:, :1024]      [2048,1024]
    gemm_nn<<<dim3(HID / 128, N_NODES / 128), 256>>>(
        pK, Wq, pA, HID, HID, LDQ, HID);
    // v, w (needs K)
    vw_kernel<<<N_NODES / 8, 256>>>(Wq, bq);
    // P = c * E A^T             [2048,2048]
    gemm_tn<false><<<dim3(N_NODES / 128, N_NODES / 128), 256>>>(
        node_emb, pA, nullptr, pP, HID, HID, HID, N_NODES, COEF);
    // sequential greedy decode (128 threads, 16 cand/thread)
    decode_kernel<<<1, 128>>>(demands, capi, depi, out);

    (void)in_sizes; (void)out_size;
}

// round 12
// speedup vs baseline: 1.2153x; 1.2153x over previous
#include <cuda_runtime.h>
#include <cstdint>

#define N_NODES 2048
#define HID 1024
#define LDQ 1026          // Wq row stride (HID + 2)
#define T_STEPS 2304      // N + N/8
#define TOUR_LEN 2305
#define COEF 0.015625f    // ALPHA / sqrt(HID) = 0.5/32, exact power of two
#define KEY_SENTINEL (-2147483647 - 1)   // INT_MIN < ordkey(-inf)

// Scratch (allocation-free rule: __device__ globals)
static __device__ float g_K[N_NODES * HID];      // 8 MB  K = E Wk^T + bk
static __device__ float g_A[N_NODES * HID];      // 8 MB  A = K Wq1
static __device__ float g_P[N_NODES * N_NODES];  // 16 MB P'[last][cand] = c*E A^T + w
static __device__ float g_v[N_NODES];
static __device__ float g_w[N_NODES];

// ---------------------------------------------------------------------------
// f32x2 packed helpers (FFMA2 — ptxas only emits via PTX fma.rn.f32x2).
// Per-lane IEEE fma.rn => bitwise identical to scalar fmaf chains.
// ---------------------------------------------------------------------------
__device__ __forceinline__ unsigned long long f2dup(float x) {
    unsigned long long r;
    asm("mov.b64 %0, {%1, %1};" : "=l"(r) : "f"(x));
    return r;
}
__device__ __forceinline__ void fma2(unsigned long long& d,
                                     unsigned long long a,
                                     unsigned long long b) {
    asm("fma.rn.f32x2 %0, %1, %2, %0;" : "+l"(d) : "l"(a), "l"(b));
}
__device__ __forceinline__ void f2unpack(unsigned long long v, float& lo, float& hi) {
    asm("mov.b64 {%0, %1}, %2;" : "=f"(lo), "=f"(hi) : "l"(v));
}

// Shared compute micro-kernel: 16 k-steps on buffer s, 8x8 microtile.
#define MICRO_COMPUTE(S)                                                      \
    do {                                                                      \
        _Pragma("unroll")                                                     \
        for (int kk = 0; kk < 16; kk++) {                                     \
            float4 a0 = *(const float4*)&As[S][kk][ty * 8];                   \
            float4 a1 = *(const float4*)&As[S][kk][ty * 8 + 4];               \
            ulonglong2 q0 = *(const ulonglong2*)&Bs[S][kk][tx * 8];           \
            ulonglong2 q1 = *(const ulonglong2*)&Bs[S][kk][tx * 8 + 4];       \
            float av[8] = {a0.x, a0.y, a0.z, a0.w, a1.x, a1.y, a1.z, a1.w};   \
            _Pragma("unroll")                                                 \
            for (int i = 0; i < 8; i++) {                                     \
                unsigned long long ad = f2dup(av[i]);                         \
                fma2(acc[i][0], ad, q0.x);                                    \
                fma2(acc[i][1], ad, q0.y);                                    \
                fma2(acc[i][2], ad, q1.x);                                    \
                fma2(acc[i][3], ad, q1.y);                                    \
            }                                                                 \
        }                                                                     \
    } while (0)

#define EPILOGUE()                                                            \
    do {                                                                      \
        _Pragma("unroll")                                                     \
        for (int i = 0; i < 8; i++) {                                         \
            int row = bm + ty * 8 + i;                                        \
            float o[8];                                                       \
            _Pragma("unroll")                                                 \
            for (int j = 0; j < 4; j++) f2unpack(acc[i][j], o[2*j], o[2*j+1]);\
            int col = bn + tx * 8;                                            \
            float4 o0, o1;                                                    \
            o0.x = o[0]*scale; o0.y = o[1]*scale; o0.z = o[2]*scale; o0.w = o[3]*scale; \
            o1.x = o[4]*scale; o1.y = o[5]*scale; o1.z = o[6]*scale; o1.w = o[7]*scale; \
            if (HAS_BIAS) {                                                   \
                o0.x += bias[col+0]; o0.y += bias[col+1];                     \
                o0.z += bias[col+2]; o0.w += bias[col+3];                     \
                o1.x += bias[col+4]; o1.y += bias[col+5];                     \
                o1.z += bias[col+6]; o1.w += bias[col+7];                     \
            }                                                                 \
            *(float4*)(C + (size_t)row * ldc + col)     = o0;                 \
            *(float4*)(C + (size_t)row * ldc + col + 4) = o1;                 \
        }                                                                     \
    } while (0)

// ---------------------------------------------------------------------------
// TN GEMM: C[m,n] = scale * sum_k A[m,k]*B[n,k] (+ bias[n]).
// ---------------------------------------------------------------------------
template <bool HAS_BIAS>
__global__ __launch_bounds__(256)
void gemm_tn(const float* __restrict__ A, const float* __restrict__ B,
             const float* __restrict__ bias, float* __restrict__ C,
             int Kd, int lda, int ldb, int ldc, float scale)
{
    __shared__ __align__(16) float As[2][16][128];
    __shared__ __align__(16) float Bs[2][16][128];
    const int tid = threadIdx.x;
    const int bm = blockIdx.y * 128, bn = blockIdx.x * 128;
    const int tx = tid & 15, ty = tid >> 4;
    const int ar = tid >> 2, ac4 = tid & 3;

    unsigned long long acc[8][4];
#pragma unroll
    for (int i = 0; i < 8; i++)
#pragma unroll
        for (int j = 0; j < 4; j++) acc[i][j] = 0ull;

    const float* Ap = A + (size_t)(bm + ar) * lda + ac4 * 4;
    const float* Bp = B + (size_t)(bn + ar) * ldb + ac4 * 4;
    float4 ra0, ra1, rb0, rb1;

#define LOADT(K0)                                                             \
    do {                                                                      \
        ra0 = __ldg((const float4*)(Ap + (K0)));                              \
        ra1 = __ldg((const float4*)(Ap + (size_t)64 * lda + (K0)));           \
        rb0 = __ldg((const float4*)(Bp + (K0)));                              \
        rb1 = __ldg((const float4*)(Bp + (size_t)64 * ldb + (K0)));           \
    } while (0)
#define STORET(S)                                                             \
    do {                                                                      \
        As[S][ac4*4+0][ar] = ra0.x; As[S][ac4*4+1][ar] = ra0.y;               \
        As[S][ac4*4+2][ar] = ra0.z; As[S][ac4*4+3][ar] = ra0.w;               \
        As[S][ac4*4+0][ar+64] = ra1.x; As[S][ac4*4+1][ar+64] = ra1.y;         \
        As[S][ac4*4+2][ar+64] = ra1.z; As[S][ac4*4+3][ar+64] = ra1.w;         \
        Bs[S][ac4*4+0][ar] = rb0.x; Bs[S][ac4*4+1][ar] = rb0.y;               \
        Bs[S][ac4*4+2][ar] = rb0.z; Bs[S][ac4*4+3][ar] = rb0.w;               \
        Bs[S][ac4*4+0][ar+64] = rb1.x; Bs[S][ac4*4+1][ar+64] = rb1.y;         \
        Bs[S][ac4*4+2][ar+64] = rb1.z; Bs[S][ac4*4+3][ar+64] = rb1.w;         \
    } while (0)

    LOADT(0);
    STORET(0);
    __syncthreads();
    const int KT = Kd / 16;
#pragma unroll 1
    for (int kt = 0; kt < KT; kt++) {
        const int s = kt & 1;
        const bool more = (kt + 1) < KT;
        if (more) LOADT((kt + 1) * 16);
        MICRO_COMPUTE(s);
        if (more) { STORET(s ^ 1); __syncthreads(); }
    }
    EPILOGUE();
#undef LOADT
#undef STORET
}

// ---------------------------------------------------------------------------
// NN GEMM: C[m,n] = sum_k A[m,k]*B[k,n], B row stride ldb (=LDQ).
// ---------------------------------------------------------------------------
__global__ __launch_bounds__(256)
void gemm_nn(const float* __restrict__ A, const float* __restrict__ B,
             float* __restrict__ C, int Kd, int lda, int ldb, int ldc)
{
    __shared__ __align__(16) float As[2][16][128];
    __shared__ __align__(16) float Bs[2][16][128];
    const int tid = threadIdx.x;
    const int bm = blockIdx.y * 128, bn = blockIdx.x * 128;
    const int tx = tid & 15, ty = tid >> 4;
    const int ar = tid >> 2, ac4 = tid & 3;
    const int br = tid >> 6, bc2 = tid & 63;
    const float scale = 1.0f;
    const bool HAS_BIAS = false;
    const float* bias = nullptr;

    unsigned long long acc[8][4];
#pragma unroll
    for (int i = 0; i < 8; i++)
#pragma unroll
        for (int j = 0; j < 4; j++) acc[i][j] = 0ull;

    const float* Ap  = A + (size_t)(bm + ar) * lda + ac4 * 4;
    const float* Bpn = B + (size_t)br * ldb + bn + bc2 * 2;
    float4 ra0, ra1;
    float2 rbn[4];

#define LOADN(K0)                                                             \
    do {                                                                      \
        ra0 = __ldg((const float4*)(Ap + (K0)));                              \
        ra1 = __ldg((const float4*)(Ap + (size_t)64 * lda + (K0)));           \
        _Pragma("unroll")                                                     \
        for (int p = 0; p < 4; p++)                                           \
            rbn[p] = *(const float2*)(Bpn + (size_t)((K0) + p * 4) * ldb);    \
    } while (0)
#define STOREN(S)                                                             \
    do {                                                                      \
        As[S][ac4*4+0][ar] = ra0.x; As[S][ac4*4+1][ar] = ra0.y;               \
        As[S][ac4*4+2][ar] = ra0.z; As[S][ac4*4+3][ar] = ra0.w;               \
        As[S][ac4*4+0][ar+64] = ra1.x; As[S][ac4*4+1][ar+64] = ra1.y;         \
        As[S][ac4*4+2][ar+64] = ra1.z; As[S][ac4*4+3][ar+64] = ra1.w;         \
        _Pragma("unroll")                                                     \
        for (int p = 0; p < 4; p++) {                                         \
            Bs[S][br + p*4][bc2*2 + 0] = rbn[p].x;                            \
            Bs[S][br + p*4][bc2*2 + 1] = rbn[p].y;                            \
        }                                                                     \
    } while (0)

    LOADN(0);
    STOREN(0);
    __syncthreads();
    const int KT = Kd / 16;
#pragma unroll 1
    for (int kt = 0; kt < KT; kt++) {
        const int s = kt & 1;
        const bool more = (kt + 1) < KT;
        if (more) LOADN((kt + 1) * 16);
        MICRO_COMPUTE(s);
        if (more) { STOREN(s ^ 1); __syncthreads(); }
    }
    EPILOGUE();
#undef LOADN
#undef STOREN
}

// ---------------------------------------------------------------------------
// v[i] = c * sum_h K[i,h]*Wq[h,1024];  w[i] = c * sum_h K[i,h]*bq[h]
// ---------------------------------------------------------------------------
__global__ __launch_bounds__(256)
void vw_kernel(const float* __restrict__ Wq, const float* __restrict__ bq)
{
    __shared__ float scol[HID];
    __shared__ float sbq[HID];
    const int tid = threadIdx.x;
    for (int h = tid; h < HID; h += 256) {
        scol[h] = Wq[(size_t)h * LDQ + HID];
        sbq[h]  = bq[h];
    }
    __syncthreads();
    const int warp = tid >> 5, lane = tid & 31;
    const int row = blockIdx.x * 8 + warp;
    const float* Kr = g_K + (size_t)row * HID;
    float vv = 0.f, ww = 0.f;
#pragma unroll 4
    for (int m = 0; m < HID / 32; m++) {
        int h = lane + m * 32;
        float k = Kr[h];
        vv = fmaf(k, scol[h], vv);
        ww = fmaf(k, sbq[h], ww);
    }
#pragma unroll
    for (int off = 16; off; off >>= 1) {
        vv += __shfl_xor_sync(0xffffffffu, vv, off);
        ww += __shfl_xor_sync(0xffffffffu, ww, off);
    }
    if (lane == 0) { g_v[row] = COEF * vv; g_w[row] = COEF * ww; }
}

// ---------------------------------------------------------------------------
// Decoder helpers: SIGNED-order-preserving float<->int key.
// ---------------------------------------------------------------------------
__device__ __forceinline__ int ordkey(float f) {
    int b = __float_as_int(f);
    return b ^ ((b >> 31) & 0x7FFFFFFF);
}
__device__ __forceinline__ float unord(int k) {
    int b = k ^ ((k >> 31) & 0x7FFFFFFF);
    return __int_as_float(b);
}
__device__ __forceinline__ int redux_max_i32(int v) {
    int r;
    asm("redux.sync.max.s32 %0, %1, 0xffffffff;" : "=r"(r) : "r"(v));
    return r;
}

// ---------------------------------------------------------------------------
// Sequential decoder (R4 skeleton + chain cuts): 256 threads, 8 cand/thread.
// s = fmaf(u, v[i], P'[last,i])   with P' = c*E A^T + w  (w pre-folded,
// bitwise-identical to computing P + w per step).
// Tree argmax, src-lane STS (no shfl), hoisted next-row LDG.
// ---------------------------------------------------------------------------
__global__ __launch_bounds__(256)
void decode_kernel(const float* __restrict__ demands,
                   const int* __restrict__ cap_ptr,
                   const int* __restrict__ depot_ptr,
                   float* __restrict__ out)
{
    __shared__ float sdem[N_NODES];
    __shared__ __align__(16) int2 red[2][8];

    const int tid = threadIdx.x;
    for (int i = tid; i < N_NODES; i += 256) sdem[i] = demands[i];

    // per-thread candidate block [tid*8, tid*8+8): invariants in registers
    float rv[8], rd[8];
    {
        const float4* pv4 = (const float4*)(g_v + tid * 8);
        const float4* pd4 = (const float4*)(demands + tid * 8);
        float4 a, b;
        a = pv4[0]; b = pv4[1];
        rv[0]=a.x; rv[1]=a.y; rv[2]=a.z; rv[3]=a.w; rv[4]=b.x; rv[5]=b.y; rv[6]=b.z; rv[7]=b.w;
        a = pd4[0]; b = pd4[1];
        rd[0]=a.x; rd[1]=a.y; rd[2]=a.z; rd[3]=a.w; rd[4]=b.x; rd[5]=b.y; rd[6]=b.z; rd[7]=b.w;
    }

    int ci = cap_ptr ? __ldg(cap_ptr) : 40;
    float cap = (ci >= 0 && ci < (1 << 23)) ? (float)ci : __int_as_float(ci);
    int depot = depot_ptr ? __ldg(depot_ptr) : 0;
    if ((unsigned)depot >= N_NODES) depot = 0;

    unsigned vis = 0;
    if ((depot >> 3) == tid) vis = 1u << (depot & 7);
    int last = depot;
    float load = cap;
    int count = 1;
    if (tid == 0) out[0] = (float)depot;
    __syncthreads();

    const int lane = tid & 31, warp = tid >> 5;
    int tstop = T_STEPS;

    // prologue: load depot row slice (software-rotated across iterations)
    const float4* Pr = (const float4*)(g_P + (size_t)last * N_NODES + tid * 8);
    float4 p0 = __ldg(Pr);
    float4 p1 = __ldg(Pr + 1);

    for (int t = 0; t < T_STEPS; t++) {
        const float u = load / cap;    // hidden under the row LDG latency
        float pv[8] = {p0.x, p0.y, p0.z, p0.w, p1.x, p1.y, p1.z, p1.w};

        // keys with feasibility folded in
        int key[8];
#pragma unroll
        for (int j = 0; j < 8; j++) {
            float s = fmaf(u, rv[j], pv[j]);           // exact (w folded into P')
            bool feas = !((vis >> j) & 1u) && (rd[j] <= load);
            key[j] = feas ? ordkey(s) : KEY_SENTINEL;
        }
        // 3-level leftmost-max tree (key, local idx)
        int k4[4], i4[4];
#pragma unroll
        for (int j = 0; j < 4; j++) {
            bool l = key[2*j] >= key[2*j+1];
            k4[j] = l ? key[2*j] : key[2*j+1];
            i4[j] = l ? 2*j : 2*j+1;
        }
        int k2a, i2a, k2b, i2b;
        { bool l = k4[0] >= k4[1]; k2a = l ? k4[0] : k4[1]; i2a = l ? i4[0] : i4[1]; }
        { bool l = k4[2] >= k4[3]; k2b = l ? k4[2] : k4[3]; i2b = l ? i4[2] : i4[3]; }
        bool l0 = k2a >= k2b;
        int bestk = l0 ? k2a : k2b;
        int besti = tid * 8 + (l0 ? i2a : i2b);

        // warp argmax: redux + ballot; the winning (lowest) lane stores directly
        int m = redux_max_i32(bestk);
        unsigned bal = __ballot_sync(0xffffffffu, bestk == m);
        if (lane == __ffs(bal) - 1) red[t & 1][warp] = make_int2(m, besti);
        __syncthreads();

        // all threads redundantly scan the 8 warp winners (4x LDS.128)
        const int4* rp = (const int4*)red[t & 1];
        int4 r0 = rp[0], r1 = rp[1], r2 = rp[2], r3 = rp[3];
        int gk = r0.x, gi = r0.y;
        if (r0.z > gk) { gk = r0.z; gi = r0.w; }
        if (r1.x > gk) { gk = r1.x; gi = r1.y; }
        if (r1.z > gk) { gk = r1.z; gi = r1.w; }
        if (r2.x > gk) { gk = r2.x; gi = r2.y; }
        if (r2.z > gk) { gk = r2.z; gi = r2.w; }
        if (r3.x > gk) { gk = r3.x; gi = r3.y; }
        if (r3.z > gk) { gk = r3.z; gi = r3.w; }

        const bool take = (gk > KEY_SENTINEL);
        last = take ? gi : depot;

        // issue next row LDG ASAP — bookkeeping below overlaps the L2 trip
        Pr = (const float4*)(g_P + (size_t)last * N_NODES + tid * 8);
        p0 = __ldg(Pr);
        p1 = __ldg(Pr + 1);

        if (take) {
            if (tid == 0) { out[1 + t] = (float)gi; out[TOUR_LEN + t] = unord(gk); }
            if ((gi >> 3) == tid) vis |= 1u << (gi & 7);
            load -= sdem[gi];
            count++;
        } else {
            if (tid == 0) { out[1 + t] = (float)depot; out[TOUR_LEN + t] = 0.0f; }
            load = cap;
            if (count == N_NODES) { tstop = t + 1; break; }
        }
    }
    for (int t2 = tstop + tid; t2 < T_STEPS; t2 += 256) {
        out[1 + t2] = (float)depot;
        out[TOUR_LEN + t2] = 0.0f;
    }
}

// ---------------------------------------------------------------------------
extern "C" void kernel_launch(void* const* d_in, const int* in_sizes, int n_in,
                              void* d_out, int out_size)
{
    const float* node_emb = (const float*)d_in[0];
    const float* demands  = (const float*)d_in[1];
    const float* Wq       = (const float*)d_in[2];
    const float* bq       = (const float*)d_in[3];
    const float* Wk       = (const float*)d_in[4];
    const float* bk       = (const float*)d_in[5];
    const int* capi = (n_in > 6) ? (const int*)d_in[6] : nullptr;
    const int* depi = (n_in > 7) ? (const int*)d_in[7] : nullptr;
    float* out = (float*)d_out;

    float *pK = nullptr, *pA = nullptr, *pP = nullptr, *pW = nullptr;
    cudaGetSymbolAddress((void**)&pK, g_K);
    cudaGetSymbolAddress((void**)&pA, g_A);
    cudaGetSymbolAddress((void**)&pP, g_P);
    cudaGetSymbolAddress((void**)&pW, g_w);

    // K = E Wk^T + bk           [2048,1024]
    gemm_tn<true><<<dim3(HID / 128, N_NODES / 128), 256>>>(
        node_emb, Wk, bk, pK, HID, HID, HID, HID, 1.0f);
    // v, w (needs K)
    vw_kernel<<<N_NODES / 8, 256>>>(Wq, bq);
    // A = K @ Wq[:, :1024]      [2048,1024]
    gemm_nn<<<dim3(HID / 128, N_NODES / 128), 256>>>(
        pK, Wq, pA, HID, HID, LDQ, HID);
    // P' = c * E A^T + w        [2048,2048]  (w folded as bias — bitwise
    // identical to adding w per step in the decoder)
    gemm_tn<true><<<dim3(N_NODES / 128, N_NODES / 128), 256>>>(
        node_emb, pA, pW, pP, HID, HID, HID, N_NODES, COEF);
    // sequential greedy decode (256 threads, 8 cand/thread)
    decode_kernel<<<1, 256>>>(demands, capi, depi, out);

    (void)in_sizes; (void)out_size;
}